// round 8
// baseline (speedup 1.0000x reference)
#include <cuda_runtime.h>
#include <cstdint>

// QuantumKANRegressor: out[b] = sum_f sum_j kan[f,j] * T_j( tanh( sum_k w[f,k]*T_{k+1}(X[b,f]) / sum_k|w[f,k]| ) )
// B=65536, F=64, DEG=16 (T_1..T_16), KAN_DEG=5 (T_0..T_5)
//
// R8 (= R6/R7 design; both prior benches died to broker infra failures):
// feature-packed f32x2. Hot dot-weights wq (16 ull = 44 regs) in REGISTERS;
// cold KAN Horner coeffs in SMEM (6 LDS.64/group, conflict-free). Register
// budget tuned for 3 CTAs/SM (85 regs) -- occupancy is the binding constraint
// (R3 at 6 warps/SMSP: issue 45%; R5 at 4 warps/SMSP: issue 26%).

typedef unsigned long long ull;

__device__ __forceinline__ ull pk2(float lo, float hi) {
    ull d; asm("mov.b64 %0, {%1, %2};" : "=l"(d) : "f"(lo), "f"(hi)); return d;
}
__device__ __forceinline__ void upk2(ull v, float& lo, float& hi) {
    asm("mov.b64 {%0, %1}, %2;" : "=f"(lo), "=f"(hi) : "l"(v));
}
__device__ __forceinline__ ull fma2(ull a, ull b, ull c) {
    ull d; asm("fma.rn.f32x2 %0, %1, %2, %3;" : "=l"(d) : "l"(a), "l"(b), "l"(c)); return d;
}
__device__ __forceinline__ ull add2(ull a, ull b) {
    ull d; asm("add.rn.f32x2 %0, %1, %2;" : "=l"(d) : "l"(a), "l"(b)); return d;
}
__device__ __forceinline__ ull mul2(ull a, ull b) {
    ull d; asm("mul.rn.f32x2 %0, %1, %2;" : "=l"(d) : "l"(a), "l"(b)); return d;
}
__device__ __forceinline__ float ex2f(float x) {
    float y; asm("ex2.approx.f32 %0, %1;" : "=f"(y) : "f"(x)); return y;
}
__device__ __forceinline__ float rcpf(float x) {
    float y; asm("rcp.approx.f32 %0, %1;" : "=f"(y) : "f"(x)); return y;
}
// tanh(f) = 1 - 2/(1 + exp(2f)); exp via ex2 (MUFU). ~1e-6 abs error on |f|<=1.
__device__ __forceinline__ float tanh_fast(float f) {
    float e = ex2f(f * 2.8853900817779268f);   // 2 * log2(e)
    float r = rcpf(e + 1.0f);
    return fmaf(-2.0f, r, 1.0f);
}

static constexpr int F    = 64;
static constexpr int DEG  = 16;
static constexpr int NBLK = 444;   // 3 CTAs/SM * 148 SMs
static constexpr int NTHR = 256;

__global__ void __launch_bounds__(NTHR, 3)
qkan_kernel(const float* __restrict__ X,
            const float* __restrict__ W,    // [F, DEG]
            const float* __restrict__ KC,   // [1, F, 6]
            float* __restrict__ out,        // [B]
            int B)
{
    // KAN Horner coefficients in SMEM: pc_s[k][lane] packed (f0=2*lane, f1=2*lane+1).
    // Lane-indexed LDS.64 -> conflict-free.
    __shared__ ull pc_s[6][32];

    const int tid  = threadIdx.x;
    const int lane = tid & 31;

    // -------- one-time preprocessing --------
    if (tid < 32) {
        // KAN Chebyshev (deg 5) -> monomial Horner coefficients, packed per lane.
        float pm[2][6];
        #pragma unroll
        for (int i = 0; i < 2; ++i) {
            const int f = 2 * tid + i;
            const float k0 = __ldg(KC + f*6+0), k1 = __ldg(KC + f*6+1), k2 = __ldg(KC + f*6+2);
            const float k3 = __ldg(KC + f*6+3), k4 = __ldg(KC + f*6+4), k5 = __ldg(KC + f*6+5);
            pm[i][0] = k0 - k2 + k4;
            pm[i][1] = k1 - 3.0f*k3 + 5.0f*k5;
            pm[i][2] = 2.0f*k2 - 8.0f*k4;
            pm[i][3] = 4.0f*k3 - 20.0f*k5;
            pm[i][4] = 8.0f*k4;
            pm[i][5] = 16.0f*k5;
        }
        #pragma unroll
        for (int k = 0; k < 6; ++k) pc_s[k][tid] = pk2(pm[0][k], pm[1][k]);
    }

    // Hot dot-weights in registers: lane owns features f0=2*lane, f1=2*lane+1.
    // Sign-folded Chebyshev: X_k = s_k*T_k, s_k = -1 for k mod 4 in {2,3};
    // recurrence X_j = fma( (j odd ? +2x : -2x), X_{j-1}, X_{j-2} ).
    // Folded weight: w'_k = lcu[f][k-1] * s_k / denom[f].
    ull wq[DEG];
    {
        float wv[2][DEG];
        float rd[2];
        #pragma unroll
        for (int i = 0; i < 2; ++i) {
            const int f = 2 * lane + i;
            float den = 0.0f;
            #pragma unroll
            for (int k = 0; k < DEG; ++k) { wv[i][k] = __ldg(W + f * DEG + k); den += fabsf(wv[i][k]); }
            rd[i] = 1.0f / den;
        }
        #pragma unroll
        for (int k = 0; k < DEG; ++k) {
            const int kk = k + 1;
            float v0 = wv[0][k] * rd[0];
            float v1 = wv[1][k] * rd[1];
            if (kk & 2) { v0 = -v0; v1 = -v1; }
            wq[k] = pk2(v0, v1);
        }
    }
    __syncthreads();

    const ull ONE2  = 0x3F8000003F800000ull;   // (1.0f, 1.0f)
    const ull NEG22 = 0xC0000000C0000000ull;   // (-2.0f, -2.0f)

    const int gw = (blockIdx.x * NTHR + tid) >> 5;
    const int nW = (gridDim.x * NTHR) >> 5;
    const int nG = B / 2;                      // 2 rows per group

    // ---- prefetch first group (2 rows, lane reads its feature pair) ----
    int g = gw;
    float2 cx0, cx1;
    if (g < nG) {
        const float2* base = (const float2*)X + (size_t)(2 * g) * 32 + lane;
        cx0 = __ldg(base);
        cx1 = __ldg(base + 32);
    }

    while (g < nG) {
        const int gn = g + nW;
        float2 nx0, nx1;
        if (gn < nG) {
            const float2* base = (const float2*)X + (size_t)(2 * gn) * 32 + lane;
            nx0 = __ldg(base);
            nx1 = __ldg(base + 32);
        }

        // ---- two independent row chains ----
        const ull x0   = pk2(cx0.x, cx0.y);
        const ull x1   = pk2(cx1.x, cx1.y);
        const ull p2x0 = add2(x0, x0),     p2x1 = add2(x1, x1);
        const ull m2x0 = mul2(x0, NEG22),  m2x1 = mul2(x1, NEG22);
        ull Xa0 = x0,                      Xa1 = x1;
        ull Xb0 = fma2(m2x0, x0, ONE2);
        ull Xb1 = fma2(m2x1, x1, ONE2);
        ull f0  = mul2(wq[0], Xa0);
        ull f1  = mul2(wq[0], Xa1);
        f0 = fma2(wq[1], Xb0, f0);
        f1 = fma2(wq[1], Xb1, f1);
        #pragma unroll
        for (int j = 3; j <= DEG; ++j) {
            const ull Xc0 = fma2((j & 1) ? p2x0 : m2x0, Xb0, Xa0);
            const ull Xc1 = fma2((j & 1) ? p2x1 : m2x1, Xb1, Xa1);
            f0 = fma2(wq[j - 1], Xc0, f0);
            f1 = fma2(wq[j - 1], Xc1, f1);
            Xa0 = Xb0; Xb0 = Xc0;
            Xa1 = Xb1; Xb1 = Xc1;
        }
        // tanh (MUFU) then deg-5 Horner (coeffs from SMEM, conflict-free)
        float l0, h0, l1, h1;
        upk2(f0, l0, h0); upk2(f1, l1, h1);
        const ull z0 = pk2(tanh_fast(l0), tanh_fast(h0));
        const ull z1 = pk2(tanh_fast(l1), tanh_fast(h1));
        const ull q5 = pc_s[5][lane], q4 = pc_s[4][lane], q3 = pc_s[3][lane];
        const ull q2 = pc_s[2][lane], q1 = pc_s[1][lane], q0 = pc_s[0][lane];
        ull t0 = fma2(q5, z0, q4);
        ull t1 = fma2(q5, z1, q4);
        t0 = fma2(t0, z0, q3); t1 = fma2(t1, z1, q3);
        t0 = fma2(t0, z0, q2); t1 = fma2(t1, z1, q2);
        t0 = fma2(t0, z0, q1); t1 = fma2(t1, z1, q1);
        t0 = fma2(t0, z0, q0); t1 = fma2(t1, z1, q0);
        float s0lo, s0hi, s1lo, s1hi;
        upk2(t0, s0lo, s0hi); upk2(t1, s1lo, s1hi);
        const float s0 = s0lo + s0hi;          // row 2g   partial (lane's 2 feats)
        const float s1 = s1lo + s1hi;          // row 2g+1 partial

        // ---- warp reduction: pack (row0, row1), 5-level 64-bit tree ----
        {
            ull m = pk2(s0, s1);
            #pragma unroll
            for (int off = 16; off; off >>= 1)
                m = add2(m, __shfl_xor_sync(0xffffffffu, m, off));
            if (lane == 0) {
                float lo, hi; upk2(m, lo, hi);
                ((float2*)out)[g] = make_float2(lo, hi);
            }
        }

        cx0 = nx0; cx1 = nx1;
        g = gn;
    }
}

extern "C" void kernel_launch(void* const* d_in, const int* in_sizes, int n_in,
                              void* d_out, int out_size)
{
    const float* X  = (const float*)d_in[0];   // [B, 64] fp32
    const float* W  = (const float*)d_in[1];   // [64, 16] fp32
    const float* KC = (const float*)d_in[2];   // [1, 64, 6] fp32
    float* out = (float*)d_out;                // [B] fp32

    const int B = in_sizes[0] / F;             // 65536

    qkan_kernel<<<NBLK, NTHR>>>(X, W, KC, out, B);
}

// round 9
// speedup vs baseline: 1.6124x; 1.6124x over previous
#include <cuda_runtime.h>
#include <cstdint>

// QuantumKANRegressor: out[b] = sum_f sum_j kan[f,j] * T_j( tanh( sum_k w[f,k]*T_{k+1}(X[b,f]) / sum_k|w[f,k]| ) )
// B=65536, F=64, DEG=16 (T_1..T_16), KAN_DEG=5 (T_0..T_5)
//
// R9: lesson from R1/R4/R5/R8 — per-thread ull weight arrays ALWAYS get
// demoted to local memory (L1-bound). So: ALL weights live in SMEM
// (conflict-free lane-indexed packed planes), feature-packed f32x2 so one
// plane serves both packed halves, R=4 rows per group so the 22 LDS.64 of
// weights amortize over 4 rows (5.5 LDS/row vs R3's 22), 4 independent
// chains for ILP, 3 CTAs/SM for latency coverage. No spillable arrays.

typedef unsigned long long ull;

__device__ __forceinline__ ull pk2(float lo, float hi) {
    ull d; asm("mov.b64 %0, {%1, %2};" : "=l"(d) : "f"(lo), "f"(hi)); return d;
}
__device__ __forceinline__ void upk2(ull v, float& lo, float& hi) {
    asm("mov.b64 {%0, %1}, %2;" : "=f"(lo), "=f"(hi) : "l"(v));
}
__device__ __forceinline__ ull fma2(ull a, ull b, ull c) {
    ull d; asm("fma.rn.f32x2 %0, %1, %2, %3;" : "=l"(d) : "l"(a), "l"(b), "l"(c)); return d;
}
__device__ __forceinline__ ull add2(ull a, ull b) {
    ull d; asm("add.rn.f32x2 %0, %1, %2;" : "=l"(d) : "l"(a), "l"(b)); return d;
}
__device__ __forceinline__ ull mul2(ull a, ull b) {
    ull d; asm("mul.rn.f32x2 %0, %1, %2;" : "=l"(d) : "l"(a), "l"(b)); return d;
}
__device__ __forceinline__ float ex2f(float x) {
    float y; asm("ex2.approx.f32 %0, %1;" : "=f"(y) : "f"(x)); return y;
}
__device__ __forceinline__ float rcpf(float x) {
    float y; asm("rcp.approx.f32 %0, %1;" : "=f"(y) : "f"(x)); return y;
}
// tanh(f) = 1 - 2/(1 + exp(2f)); exp via ex2 (MUFU). ~1e-6 abs error on |f|<=1.
__device__ __forceinline__ float tanh_fast(float f) {
    float e = ex2f(f * 2.8853900817779268f);   // 2 * log2(e)
    float r = rcpf(e + 1.0f);
    return fmaf(-2.0f, r, 1.0f);
}

static constexpr int F    = 64;
static constexpr int DEG  = 16;
static constexpr int NBLK = 444;   // 3 CTAs/SM * 148 SMs
static constexpr int NTHR = 256;
static constexpr int R    = 4;     // rows per warp-iteration

__global__ void __launch_bounds__(NTHR, 3)
qkan_kernel(const float* __restrict__ X,
            const float* __restrict__ W,    // [F, DEG]
            const float* __restrict__ KC,   // [1, F, 6]
            float* __restrict__ out,        // [B]
            int B)
{
    // Packed weight planes in SMEM. Element [k][lane] holds (w_{f0,k}, w_{f1,k})
    // for the lane's features f0=2*lane, f1=2*lane+1. Lane-indexed LDS.64 is
    // conflict-free (consecutive 8B across lanes).
    __shared__ ull wq_s[DEG][32];
    __shared__ ull pc_s[6][32];

    const int tid  = threadIdx.x;
    const int lane = tid & 31;

    // -------- one-time preprocessing (warp 0 of the block) --------
    if (tid < 32) {
        // Sign-folded, denom-folded dot weights, packed per lane.
        // X_k = s_k*T_k with s_k = -1 for k mod 4 in {2,3};
        // recurrence X_j = fma( (j odd ? +2x : -2x), X_{j-1}, X_{j-2} ).
        float v[2][DEG];
        #pragma unroll
        for (int i = 0; i < 2; ++i) {
            const int f = 2 * tid + i;
            float den = 0.0f;
            #pragma unroll
            for (int k = 0; k < DEG; ++k) { v[i][k] = __ldg(W + f * DEG + k); den += fabsf(v[i][k]); }
            const float rd = 1.0f / den;
            #pragma unroll
            for (int k = 0; k < DEG; ++k) {
                float w = v[i][k] * rd;
                if ((k + 1) & 2) w = -w;
                v[i][k] = w;
            }
        }
        #pragma unroll
        for (int k = 0; k < DEG; ++k) wq_s[k][tid] = pk2(v[0][k], v[1][k]);

        // KAN Chebyshev (deg 5) -> monomial Horner coefficients, packed per lane.
        float pm[2][6];
        #pragma unroll
        for (int i = 0; i < 2; ++i) {
            const int f = 2 * tid + i;
            const float k0 = __ldg(KC + f*6+0), k1 = __ldg(KC + f*6+1), k2 = __ldg(KC + f*6+2);
            const float k3 = __ldg(KC + f*6+3), k4 = __ldg(KC + f*6+4), k5 = __ldg(KC + f*6+5);
            pm[i][0] = k0 - k2 + k4;
            pm[i][1] = k1 - 3.0f*k3 + 5.0f*k5;
            pm[i][2] = 2.0f*k2 - 8.0f*k4;
            pm[i][3] = 4.0f*k3 - 20.0f*k5;
            pm[i][4] = 8.0f*k4;
            pm[i][5] = 16.0f*k5;
        }
        #pragma unroll
        for (int k = 0; k < 6; ++k) pc_s[k][tid] = pk2(pm[0][k], pm[1][k]);
    }
    __syncthreads();

    const ull ONE2  = 0x3F8000003F800000ull;   // (1.0f, 1.0f)
    const ull NEG22 = 0xC0000000C0000000ull;   // (-2.0f, -2.0f)

    const int gw = (blockIdx.x * NTHR + tid) >> 5;
    const int nW = (gridDim.x * NTHR) >> 5;
    const int nG = B / R;                      // groups of R rows (B % 4 == 0)

    // ---- prefetch first group ----
    int g = gw;
    float2 cx0, cx1, cx2, cx3;
    if (g < nG) {
        const float2* base = (const float2*)X + (size_t)(R * g) * 32 + lane;
        cx0 = __ldg(base);
        cx1 = __ldg(base + 32);
        cx2 = __ldg(base + 64);
        cx3 = __ldg(base + 96);
    }

    while (g < nG) {
        const int gn = g + nW;
        float2 nx0, nx1, nx2, nx3;
        if (gn < nG) {
            const float2* base = (const float2*)X + (size_t)(R * gn) * 32 + lane;
            nx0 = __ldg(base);
            nx1 = __ldg(base + 32);
            nx2 = __ldg(base + 64);
            nx3 = __ldg(base + 96);
        }

        // ---- 4 independent row chains, weights broadcast from SMEM ----
        const ull x0 = pk2(cx0.x, cx0.y);
        const ull x1 = pk2(cx1.x, cx1.y);
        const ull x2 = pk2(cx2.x, cx2.y);
        const ull x3 = pk2(cx3.x, cx3.y);
        const ull p0 = add2(x0, x0), p1 = add2(x1, x1), p2 = add2(x2, x2), p3 = add2(x3, x3);
        const ull m0 = mul2(x0, NEG22), m1 = mul2(x1, NEG22), m2 = mul2(x2, NEG22), m3 = mul2(x3, NEG22);
        ull Xa0 = x0, Xa1 = x1, Xa2 = x2, Xa3 = x3;
        ull Xb0 = fma2(m0, x0, ONE2);
        ull Xb1 = fma2(m1, x1, ONE2);
        ull Xb2 = fma2(m2, x2, ONE2);
        ull Xb3 = fma2(m3, x3, ONE2);
        ull f0, f1, f2, f3;
        {
            const ull w0 = wq_s[0][lane];
            f0 = mul2(w0, Xa0); f1 = mul2(w0, Xa1); f2 = mul2(w0, Xa2); f3 = mul2(w0, Xa3);
            const ull w1 = wq_s[1][lane];
            f0 = fma2(w1, Xb0, f0); f1 = fma2(w1, Xb1, f1);
            f2 = fma2(w1, Xb2, f2); f3 = fma2(w1, Xb3, f3);
        }
        #pragma unroll
        for (int j = 3; j <= DEG; ++j) {
            const ull w = wq_s[j - 1][lane];
            const ull Xc0 = fma2((j & 1) ? p0 : m0, Xb0, Xa0);
            const ull Xc1 = fma2((j & 1) ? p1 : m1, Xb1, Xa1);
            const ull Xc2 = fma2((j & 1) ? p2 : m2, Xb2, Xa2);
            const ull Xc3 = fma2((j & 1) ? p3 : m3, Xb3, Xa3);
            f0 = fma2(w, Xc0, f0); f1 = fma2(w, Xc1, f1);
            f2 = fma2(w, Xc2, f2); f3 = fma2(w, Xc3, f3);
            Xa0 = Xb0; Xb0 = Xc0;  Xa1 = Xb1; Xb1 = Xc1;
            Xa2 = Xb2; Xb2 = Xc2;  Xa3 = Xb3; Xb3 = Xc3;
        }

        // tanh (MUFU) then deg-5 Horner (coeffs broadcast from SMEM)
        float a0, b0, a1, b1, a2, b2, a3, b3;
        upk2(f0, a0, b0); upk2(f1, a1, b1); upk2(f2, a2, b2); upk2(f3, a3, b3);
        const ull z0 = pk2(tanh_fast(a0), tanh_fast(b0));
        const ull z1 = pk2(tanh_fast(a1), tanh_fast(b1));
        const ull z2 = pk2(tanh_fast(a2), tanh_fast(b2));
        const ull z3 = pk2(tanh_fast(a3), tanh_fast(b3));
        const ull q5 = pc_s[5][lane], q4 = pc_s[4][lane], q3 = pc_s[3][lane];
        const ull q2 = pc_s[2][lane], q1 = pc_s[1][lane], q0 = pc_s[0][lane];
        ull t0 = fma2(q5, z0, q4), t1 = fma2(q5, z1, q4);
        ull t2 = fma2(q5, z2, q4), t3 = fma2(q5, z3, q4);
        t0 = fma2(t0, z0, q3); t1 = fma2(t1, z1, q3); t2 = fma2(t2, z2, q3); t3 = fma2(t3, z3, q3);
        t0 = fma2(t0, z0, q2); t1 = fma2(t1, z1, q2); t2 = fma2(t2, z2, q2); t3 = fma2(t3, z3, q2);
        t0 = fma2(t0, z0, q1); t1 = fma2(t1, z1, q1); t2 = fma2(t2, z2, q1); t3 = fma2(t3, z3, q1);
        t0 = fma2(t0, z0, q0); t1 = fma2(t1, z1, q0); t2 = fma2(t2, z2, q0); t3 = fma2(t3, z3, q0);
        float s0, s1, s2, s3;
        { float lo, hi; upk2(t0, lo, hi); s0 = lo + hi; }
        { float lo, hi; upk2(t1, lo, hi); s1 = lo + hi; }
        { float lo, hi; upk2(t2, lo, hi); s2 = lo + hi; }
        { float lo, hi; upk2(t3, lo, hi); s3 = lo + hi; }

        // ---- folded warp reduction: 4 rows -> 2 packed values, 5 levels ----
        {
            const ull A  = pk2(s0, s1);                  // rows Rg, Rg+1
            const ull Bp = pk2(s2, s3);                  // rows Rg+2, Rg+3
            ull m = (lane & 16) ? Bp : A;
            ull o = (lane & 16) ? A  : Bp;
            m = add2(m, __shfl_xor_sync(0xffffffffu, o, 16));
            #pragma unroll
            for (int off = 8; off; off >>= 1)
                m = add2(m, __shfl_xor_sync(0xffffffffu, m, off));
            if ((lane & 15) == 0) {
                float lo, hi; upk2(m, lo, hi);
                // lane 0 -> rows (Rg, Rg+1); lane 16 -> rows (Rg+2, Rg+3)
                ((float2*)out)[2 * g + (lane >> 4)] = make_float2(lo, hi);
            }
        }

        cx0 = nx0; cx1 = nx1; cx2 = nx2; cx3 = nx3;
        g = gn;
    }
}

extern "C" void kernel_launch(void* const* d_in, const int* in_sizes, int n_in,
                              void* d_out, int out_size)
{
    const float* X  = (const float*)d_in[0];   // [B, 64] fp32
    const float* W  = (const float*)d_in[1];   // [64, 16] fp32
    const float* KC = (const float*)d_in[2];   // [1, 64, 6] fp32
    float* out = (float*)d_out;                // [B] fp32

    const int B = in_sizes[0] / F;             // 65536

    qkan_kernel<<<NBLK, NTHR>>>(X, W, KC, out, B);
}